// round 15
// baseline (speedup 1.0000x reference)
#include <cuda_runtime.h>
#include <cuda_fp16.h>
#include <cstdint>
#include <math.h>

// ============================================================================
// ConditionedLatentSDETransition — R15: persistent mega-kernel
//   One kernel, grid = 296 CTAs (2/SM x 148, co-residency guaranteed by
//   __launch_bounds__(256,2) + 80KB smem), phases separated by a
//   sense-reversing software global barrier. GEMM tile code identical to R14
//   (fp16 HMMA, 4-stage cp.async, ldmatrix, half2 BN-in-staging).
//   Phases/step: MODE0 (384 tiles) | bn1 | MODE1 (256) | bn2 | MODE2 (256) |
//   z_update  — then MODE3 (128) | yt.
// ============================================================================

#define BM 128
#define BK 32
#define KS_LD 40
#define NSTG 4
#define SMEM_SZ (2 * NSTG * BM * KS_LD * 2)   // 81920 bytes

#define BATCH 4096
#define DDIM  512
#define HDIM  1024
#define NSTEPS 8
#define NCTA 296

// ---- scratch (device globals; no allocation allowed) ----
__device__ float  g_zbuf[BATCH * DDIM];
__device__ float  g_psum [64 * HDIM];
__device__ float  g_psum2[64 * HDIM];
__device__ unsigned g_cnt = 0;
__device__ unsigned g_gen = 0;

__device__ __half g_sch[HDIM];
__device__ __half g_shh[HDIM];
__device__ __half g_zh [BATCH * DDIM];
__device__ __half g_A1h[BATCH * HDIM];
__device__ __half g_A2h[BATCH * HDIM];
__device__ __half g_Th [BATCH * DDIM];
__device__ __half g_Fh [BATCH * DDIM];
__device__ __half g_Gh [BATCH * DDIM];
__device__ __half g_W1h [HDIM * DDIM];
__device__ __half g_W2h [HDIM * HDIM];
__device__ __half g_W3h [DDIM * HDIM];
__device__ __half g_Wd1h[DDIM * DDIM];
__device__ __half g_Wd2h[DDIM * DDIM];
__device__ __half g_Bsh [DDIM * 64];
__device__ __half g_uth [BATCH * 64];

__device__ __forceinline__ float softplus_f(float x) {
    return fmaxf(x, 0.f) + log1pf(expf(-fabsf(x)));   // jax.nn.softplus
}
__device__ __forceinline__ void cp16(void* sdst, const void* gsrc) {
    uint32_t sa = (uint32_t)__cvta_generic_to_shared(sdst);
    asm volatile("cp.async.cg.shared.global [%0], [%1], 16;" :: "r"(sa), "l"(gsrc));
}
__device__ __forceinline__ void cp_commit() { asm volatile("cp.async.commit_group;"); }
__device__ __forceinline__ void cp_wait2()  { asm volatile("cp.async.wait_group 2;"); }
__device__ __forceinline__ void ldsm4(uint32_t* r, const void* p) {
    uint32_t a = (uint32_t)__cvta_generic_to_shared(p);
    asm volatile("ldmatrix.sync.aligned.m8n8.x4.shared.b16 {%0,%1,%2,%3}, [%4];"
                 : "=r"(r[0]), "=r"(r[1]), "=r"(r[2]), "=r"(r[3]) : "r"(a));
}
__device__ __forceinline__ void mma_f16(float* c, const uint32_t* a, const uint32_t* b) {
    asm volatile(
        "mma.sync.aligned.m16n8k16.row.col.f32.f16.f16.f32 "
        "{%0,%1,%2,%3}, {%4,%5,%6,%7}, {%8,%9}, {%0,%1,%2,%3};\n"
        : "+f"(c[0]), "+f"(c[1]), "+f"(c[2]), "+f"(c[3])
        : "r"(a[0]), "r"(a[1]), "r"(a[2]), "r"(a[3]), "r"(b[0]), "r"(b[1]));
}

// ---- software global barrier (all NCTA CTAs co-resident by construction) ----
__device__ __forceinline__ void gbar(unsigned& lg) {
    __syncthreads();
    if (threadIdx.x == 0) {
        __threadfence();
        if (atomicAdd(&g_cnt, 1u) == NCTA - 1u) {
            g_cnt = 0u;
            __threadfence();
            atomicAdd(&g_gen, 1u);
        } else {
            while (*(volatile unsigned*)&g_gen == lg) __nanosleep(64);
        }
    }
    __syncthreads();
    __threadfence();
    lg++;
}

// ---------------------------------------------------------------------------
// GEMM tile (identical math to R14's gemm16). MODE semantics unchanged.
// ---------------------------------------------------------------------------
template<int MODE>
__device__ __forceinline__ void gemm_tile(
    __half* sh, int bx, int by,
    const float* __restrict__ bias_a, const float* __restrict__ bias_b,
    float dtv, float* __restrict__ dout)
{
    __half* Asm = sh;
    __half* Bsm = sh + NSTG * BM * KS_LD;

    const int tid = threadIdx.x, lane = tid & 31, wid = tid >> 5;
    const int wm = wid >> 2, wn = wid & 3, grp = lane >> 2, qk = lane & 3;
    const int bm = by * BM;
    const int row0 = tid >> 2, seg8 = (tid & 3) << 3;

    bool regA = true;
    int K;
    const __half *Aop, *Wslab;
    if (MODE == 0) {
        regA = bx < 8; K = 512; Aop = g_zh;
        Wslab = regA ? g_W1h + (size_t)bx * 128 * 512
                     : g_Wd1h + (size_t)(bx - 8) * 128 * 512;
    } else if (MODE == 1) {
        K = 1024; Aop = g_A1h;
        Wslab = g_W2h + (size_t)bx * 128 * 1024;
    } else if (MODE == 2) {
        regA = bx < 4; K = regA ? 1024 : 512;
        Aop  = regA ? g_A2h : g_Th;
        Wslab = regA ? g_W3h + (size_t)bx * 128 * 1024
                     : g_Wd2h + (size_t)(bx - 4) * 128 * 512;
    } else {
        K = 64; Aop = g_uth;
        Wslab = g_Bsh + (size_t)bx * 128 * 64;
    }
    const bool trA = (MODE == 1) || (MODE == 2 && regA);

    const __half* Ap0 = Aop + (size_t)(bm + row0) * K + seg8;
    const __half* Ap1 = Ap0 + (size_t)64 * K;
    const __half* Wp0 = Wslab + (size_t)row0 * K + seg8;
    const __half* Wp1 = Wp0 + (size_t)64 * K;

    float c[4][4][4];
#pragma unroll
    for (int mi = 0; mi < 4; mi++)
#pragma unroll
        for (int ni = 0; ni < 4; ni++)
#pragma unroll
            for (int j = 0; j < 4; j++) c[mi][ni][j] = 0.f;

    const int a_r = lane & 15;
    const int a_k = (lane >> 4) << 3;
    const int b_r = (lane & 7) + ((lane >> 4) << 3);
    const int b_k = ((lane >> 3) & 1) << 3;

    uint4 a0r, a1r;

    auto ldgA = [&](int t) {
        const size_t o = (size_t)t * BK;
        a0r = *(const uint4*)(Ap0 + o);
        a1r = *(const uint4*)(Ap1 + o);
    };
    auto cpA = [&](int t, int slot) {
        const size_t o = (size_t)t * BK;
        cp16(Asm + (slot * BM + row0)      * KS_LD + seg8, Ap0 + o);
        cp16(Asm + (slot * BM + row0 + 64) * KS_LD + seg8, Ap1 + o);
    };
    auto cpB = [&](int t, int slot) {
        const size_t o = (size_t)t * BK;
        cp16(Bsm + (slot * BM + row0)      * KS_LD + seg8, Wp0 + o);
        cp16(Bsm + (slot * BM + row0 + 64) * KS_LD + seg8, Wp1 + o);
    };
    auto trsts = [&](int t, int slot) {
        const int kb = t * BK + seg8;
        uint4 sc = *(const uint4*)(g_sch + kb);
        uint4 sf = *(const uint4*)(g_shh + kb);
        __half2* s2 = (__half2*)&sc;
        __half2* f2 = (__half2*)&sf;
        uint4 o0 = a0r, o1 = a1r;
        __half2* h0 = (__half2*)&o0;
        __half2* h1 = (__half2*)&o1;
        const __half2 z2 = __float2half2_rn(0.f);
#pragma unroll
        for (int q = 0; q < 4; q++) {
            h0[q] = __hmax2(__hfma2(h0[q], s2[q], f2[q]), z2);
            h1[q] = __hmax2(__hfma2(h1[q], s2[q], f2[q]), z2);
        }
        *(uint4*)&Asm[(slot * BM + row0)      * KS_LD + seg8] = o0;
        *(uint4*)&Asm[(slot * BM + row0 + 64) * KS_LD + seg8] = o1;
    };

    const int T = K / BK;

#pragma unroll
    for (int p = 0; p < 3; p++) {
        if (p < T) {
            if (trA) ldgA(p); else cpA(p, p);
            cpB(p, p);
            cp_commit();
            if (trA) trsts(p, p);
        } else {
            cp_commit();
        }
    }

    for (int t = 0; t < T; t++) {
        cp_wait2();
        __syncthreads();

        const int tf = t + 3;
        const int slot = tf & 3;
        const bool have = tf < T;
        if (have) {
            if (trA) ldgA(tf); else cpA(tf, slot);
            cpB(tf, slot);
        }
        cp_commit();

        const int sb = t & 3;
#pragma unroll
        for (int ks = 0; ks < 2; ks++) {
            const int kk = ks * 16;
            uint32_t af[4][4], bf[4][2];
#pragma unroll
            for (int mi = 0; mi < 4; mi++)
                ldsm4(af[mi], Asm + (sb * BM + wm * 64 + mi * 16 + a_r) * KS_LD + kk + a_k);
#pragma unroll
            for (int nip = 0; nip < 2; nip++) {
                uint32_t tt[4];
                ldsm4(tt, Bsm + (sb * BM + wn * 32 + nip * 16 + b_r) * KS_LD + kk + b_k);
                bf[2 * nip][0] = tt[0]; bf[2 * nip][1] = tt[1];
                bf[2 * nip + 1][0] = tt[2]; bf[2 * nip + 1][1] = tt[3];
            }
#pragma unroll
            for (int mi = 0; mi < 4; mi++)
#pragma unroll
                for (int ni = 0; ni < 4; ni++)
                    mma_f16(c[mi][ni], af[mi], bf[ni]);
        }

        if (have && trA) trsts(tf, slot);
    }

    // ---- epilogue ----
    float s1x[4], s1y[4], s2x[4], s2y[4];
    const bool do_stats = (MODE == 1) || (MODE == 0 && regA);
    if (do_stats) {
#pragma unroll
        for (int ni = 0; ni < 4; ni++) { s1x[ni]=0.f; s1y[ni]=0.f; s2x[ni]=0.f; s2y[ni]=0.f; }
    }

#pragma unroll
    for (int mi = 0; mi < 4; mi++) {
#pragma unroll
        for (int ni = 0; ni < 4; ni++) {
            const int r0 = bm + wm * 64 + mi * 16 + grp;
            const int lc = wn * 32 + ni * 8 + (qk << 1);
#pragma unroll
            for (int h = 0; h < 2; h++) {
                const int r = r0 + h * 8;
                const float ax = c[mi][ni][2 * h];
                const float ay = c[mi][ni][2 * h + 1];
                if (MODE == 0) {
                    if (regA) {
                        const int cn = bx * 128 + lc;
                        const size_t off = (size_t)r * HDIM + cn;
                        float2 b2 = *(const float2*)(bias_a + cn);
                        float vx = ax + b2.x, vy = ay + b2.y;
                        *(__half2*)(g_A1h + off) = __floats2half2_rn(vx, vy);
                        s1x[ni] += vx; s2x[ni] = fmaf(vx, vx, s2x[ni]);
                        s1y[ni] += vy; s2y[ni] = fmaf(vy, vy, s2y[ni]);
                    } else {
                        const int cn = (bx - 8) * 128 + lc;
                        const size_t off = (size_t)r * DDIM + cn;
                        float2 b2 = *(const float2*)(bias_b + cn);
                        *(__half2*)(g_Th + off) =
                            __floats2half2_rn(tanhf(ax + b2.x), tanhf(ay + b2.y));
                    }
                } else if (MODE == 1) {
                    const int cn = bx * 128 + lc;
                    const size_t off = (size_t)r * HDIM + cn;
                    float2 b2 = *(const float2*)(bias_a + cn);
                    float vx = ax + b2.x, vy = ay + b2.y;
                    *(__half2*)(g_A2h + off) = __floats2half2_rn(vx, vy);
                    s1x[ni] += vx; s2x[ni] = fmaf(vx, vx, s2x[ni]);
                    s1y[ni] += vy; s2y[ni] = fmaf(vy, vy, s2y[ni]);
                } else if (MODE == 2) {
                    if (regA) {
                        const int cn = bx * 128 + lc;
                        const size_t off = (size_t)r * DDIM + cn;
                        float2 b2 = *(const float2*)(bias_a + cn);
                        *(__half2*)(g_Fh + off) = __floats2half2_rn(ax + b2.x, ay + b2.y);
                    } else {
                        const int cn = (bx - 4) * 128 + lc;
                        const size_t off = (size_t)r * DDIM + cn;
                        float2 b2 = *(const float2*)(bias_b + cn);
                        *(__half2*)(g_Gh + off) =
                            __floats2half2_rn(softplus_f(ax + b2.x) + 1e-5f,
                                              softplus_f(ay + b2.y) + 1e-5f);
                    }
                } else { // MODE 3
                    const int cn = bx * 128 + lc;
                    const size_t off = (size_t)r * DDIM + cn;
                    float2 zf = *(const float2*)(g_zbuf + off);
                    zf.x = fmaf(dtv, ax, zf.x);
                    zf.y = fmaf(dtv, ay, zf.y);
                    *(float2*)(g_zbuf + off) = zf;
                    *(float2*)(dout + off)   = zf;
                }
            }
        }
    }

    if (do_stats) {
        const int slot = by * 2 + wm;
#pragma unroll
        for (int ni = 0; ni < 4; ni++) {
            float a = s1x[ni], b = s1y[ni], p = s2x[ni], q = s2y[ni];
#pragma unroll
            for (int m = 4; m <= 16; m <<= 1) {
                a += __shfl_xor_sync(0xffffffffu, a, m);
                b += __shfl_xor_sync(0xffffffffu, b, m);
                p += __shfl_xor_sync(0xffffffffu, p, m);
                q += __shfl_xor_sync(0xffffffffu, q, m);
            }
            if (lane < 4) {
                const int cn = bx * 128 + wn * 32 + ni * 8 + (qk << 1);
                *(float2*)&g_psum [slot * HDIM + cn] = make_float2(a, b);
                *(float2*)&g_psum2[slot * HDIM + cn] = make_float2(p, q);
            }
        }
    }
    __syncthreads();   // smem dead before next tile/phase reuses it
}

// ---------------------------------------------------------------------------
// BN final reduce for one 64-col block -> fp16 scale/shift (dyn-smem scratch)
// ---------------------------------------------------------------------------
__device__ __forceinline__ void bnstat_tile(float* scr, int blk,
                                            const float* __restrict__ g,
                                            const float* __restrict__ be)
{
    float* sm1 = scr;
    float* sm2 = scr + 256;
    const int tid = threadIdx.x;
    const int cl  = tid & 63;
    const int r0  = tid >> 6;
    const int c   = blk * 64 + cl;
    float s = 0.f, s2 = 0.f;
#pragma unroll
    for (int r = r0; r < 64; r += 4) {
        s  += g_psum [r * HDIM + c];
        s2 += g_psum2[r * HDIM + c];
    }
    sm1[tid] = s; sm2[tid] = s2;
    __syncthreads();
    if (tid < 64) {
        s  = sm1[tid] + sm1[tid + 64] + sm1[tid + 128] + sm1[tid + 192];
        s2 = sm2[tid] + sm2[tid + 64] + sm2[tid + 128] + sm2[tid + 192];
        const float mu  = s * (1.f / (float)BATCH);
        const float var = fmaf(-mu, mu, s2 * (1.f / (float)BATCH));
        const int cc = blk * 64 + tid;
        const float sc = g[cc] / sqrtf(var + 1e-5f);
        g_sch[cc] = __float2half(sc);
        g_shh[cc] = __float2half(fmaf(-mu, sc, be[cc]));
    }
    __syncthreads();
}

__device__ __forceinline__ void cvt_seg(const float* __restrict__ s,
                                        __half* __restrict__ d, int n,
                                        int gtid, int gstride)
{
    for (int i = gtid * 8; i < n; i += gstride * 8) {
        float4 v0 = *(const float4*)(s + i);
        float4 v1 = *(const float4*)(s + i + 4);
        __half2 h0 = __floats2half2_rn(v0.x, v0.y);
        __half2 h1 = __floats2half2_rn(v0.z, v0.w);
        __half2 h2 = __floats2half2_rn(v1.x, v1.y);
        __half2 h3 = __floats2half2_rn(v1.z, v1.w);
        uint4 u;
        u.x = *(uint32_t*)&h0; u.y = *(uint32_t*)&h1;
        u.z = *(uint32_t*)&h2; u.w = *(uint32_t*)&h3;
        *(uint4*)(d + i) = u;
    }
}

// ---------------------------------------------------------------------------
// THE persistent kernel
// ---------------------------------------------------------------------------
__global__ __launch_bounds__(256, 2)
void mega(const float* __restrict__ z_dyn, const float* __restrict__ dtp,
          const float* __restrict__ ut,   const float* __restrict__ eps,
          const float* __restrict__ b1,  const float* __restrict__ g1,  const float* __restrict__ be1,
          const float* __restrict__ b2,  const float* __restrict__ g2,  const float* __restrict__ be2,
          const float* __restrict__ b3,
          const float* __restrict__ bd1, const float* __restrict__ bd2,
          const float* __restrict__ W1,  const float* __restrict__ W2,  const float* __restrict__ W3,
          const float* __restrict__ Wd1, const float* __restrict__ Wd2,
          const float* __restrict__ Bsde,
          const float* __restrict__ Cm,  const float* __restrict__ Dm,
          float* __restrict__ out)
{
    extern __shared__ __half sh[];
    const int bid = blockIdx.x;
    const int tid = threadIdx.x;
    const int gtid = bid * 256 + tid;
    const int gstride = NCTA * 256;

    unsigned lg = *(volatile unsigned*)&g_gen;   // sampled before any barrier can fire
    const float dtv = *dtp;
    const float hstep = dtv * (1.f / (float)NSTEPS);
    const float sqh   = sqrtf(fabsf(hstep) + 1e-8f);

    // ---- phase: fp16 conversions ----
    cvt_seg(W1,   g_W1h,  HDIM * DDIM, gtid, gstride);
    cvt_seg(W2,   g_W2h,  HDIM * HDIM, gtid, gstride);
    cvt_seg(W3,   g_W3h,  DDIM * HDIM, gtid, gstride);
    cvt_seg(Wd1,  g_Wd1h, DDIM * DDIM, gtid, gstride);
    cvt_seg(Wd2,  g_Wd2h, DDIM * DDIM, gtid, gstride);
    cvt_seg(Bsde, g_Bsh,  DDIM * 64,   gtid, gstride);
    cvt_seg(ut,   g_uth,  BATCH * 64,  gtid, gstride);
    cvt_seg(z_dyn, g_zh,  BATCH * DDIM, gtid, gstride);
    gbar(lg);

    for (int s = 0; s < NSTEPS; s++) {
        // ---- MODE0: 384 tiles ----
        for (int t = bid; t < 384; t += NCTA)
            gemm_tile<0>(sh, t % 12, t / 12, b1, bd1, dtv, nullptr);
        gbar(lg);
        // ---- BN1 finish ----
        if (bid < 16) bnstat_tile((float*)sh, bid, g1, be1);
        gbar(lg);
        // ---- MODE1: 256 tiles ----
        if (bid < 256) gemm_tile<1>(sh, bid & 7, bid >> 3, b2, nullptr, dtv, nullptr);
        gbar(lg);
        // ---- BN2 finish ----
        if (bid < 16) bnstat_tile((float*)sh, bid, g2, be2);
        gbar(lg);
        // ---- MODE2: 256 tiles ----
        if (bid < 256) gemm_tile<2>(sh, bid & 7, bid >> 3, b3, bd2, dtv, nullptr);
        gbar(lg);
        // ---- Euler-Maruyama update ----
        {
            const float* zin = (s == 0) ? z_dyn : g_zbuf;
            const float* eps_s = eps + (size_t)s * BATCH * DDIM;
            for (int i4 = gtid; i4 < BATCH * DDIM / 4; i4 += gstride) {
                float4 z = ((const float4*)zin)[i4];
                float4 e = ((const float4*)eps_s)[i4];
                uint2 fu = *(const uint2*)(g_Fh + (size_t)i4 * 4);
                uint2 gu = *(const uint2*)(g_Gh + (size_t)i4 * 4);
                float2 f01 = __half22float2(*(__half2*)&fu.x);
                float2 f23 = __half22float2(*(__half2*)&fu.y);
                float2 g01 = __half22float2(*(__half2*)&gu.x);
                float2 g23 = __half22float2(*(__half2*)&gu.y);
                z.x = z.x + hstep * f01.x + sqh * g01.x * e.x;
                z.y = z.y + hstep * f01.y + sqh * g01.y * e.y;
                z.z = z.z + hstep * f23.x + sqh * g23.x * e.z;
                z.w = z.w + hstep * f23.y + sqh * g23.y * e.w;
                ((float4*)g_zbuf)[i4] = z;
                __half2 h0 = __floats2half2_rn(z.x, z.y);
                __half2 h1 = __floats2half2_rn(z.z, z.w);
                uint2 u; u.x = *(uint32_t*)&h0; u.y = *(uint32_t*)&h1;
                *(uint2*)(g_zh + (size_t)i4 * 4) = u;
            }
        }
        gbar(lg);
    }

    // ---- MODE3: z_next = z + dt*(ut @ B^T) -> zbuf & out ----
    if (bid < 128) gemm_tile<3>(sh, bid & 3, bid >> 2, nullptr, nullptr, dtv, out);
    gbar(lg);

    // ---- yt = z_next @ C^T + (ut*dt) @ D^T ----
    for (int i = gtid; i < BATCH * 25; i += gstride) {
        const int r = i / 25;
        const int n = i - r * 25;
        const float4* zr = (const float4*)(g_zbuf + (size_t)r * DDIM);
        const float4* cr = (const float4*)(Cm + (size_t)n * DDIM);
        float acc = 0.f;
#pragma unroll 8
        for (int k = 0; k < DDIM / 4; k++) {
            float4 a = zr[k], b = cr[k];
            acc += a.x * b.x + a.y * b.y + a.z * b.z + a.w * b.w;
        }
        const float4* ur = (const float4*)(ut + (size_t)r * 64);
        const float4* dr = (const float4*)(Dm + (size_t)n * 64);
        float acc2 = 0.f;
#pragma unroll
        for (int k = 0; k < 16; k++) {
            float4 a = ur[k], b = dr[k];
            acc2 += a.x * b.x + a.y * b.y + a.z * b.z + a.w * b.w;
        }
        out[(size_t)BATCH * DDIM + i] = acc + dtv * acc2;
    }
}

// ===========================================================================
extern "C" void kernel_launch(void* const* d_in, const int* in_sizes, int n_in,
                              void* d_out, int out_size)
{
    (void)in_sizes; (void)n_in; (void)out_size;

    const float* z_dyn = (const float*)d_in[0];
    /* d_in[1] = z_static : unused by reference */
    const float* dtp   = (const float*)d_in[2];
    const float* ut    = (const float*)d_in[3];
    const float* eps   = (const float*)d_in[4];
    const float* W1  = (const float*)d_in[5];
    const float* b1  = (const float*)d_in[6];
    const float* g1  = (const float*)d_in[7];
    const float* be1 = (const float*)d_in[8];
    const float* W2  = (const float*)d_in[9];
    const float* b2  = (const float*)d_in[10];
    const float* g2  = (const float*)d_in[11];
    const float* be2 = (const float*)d_in[12];
    const float* W3  = (const float*)d_in[13];
    const float* b3  = (const float*)d_in[14];
    const float* Wd1 = (const float*)d_in[15];
    const float* bd1 = (const float*)d_in[16];
    const float* Wd2 = (const float*)d_in[17];
    const float* bd2 = (const float*)d_in[18];
    const float* Bsde= (const float*)d_in[19];
    const float* Cm  = (const float*)d_in[20];
    const float* Dm  = (const float*)d_in[21];
    float* out = (float*)d_out;

    cudaFuncSetAttribute(mega, cudaFuncAttributeMaxDynamicSharedMemorySize, SMEM_SZ);

    mega<<<NCTA, 256, SMEM_SZ>>>(z_dyn, dtp, ut, eps,
                                 b1, g1, be1, b2, g2, be2, b3, bd1, bd2,
                                 W1, W2, W3, Wd1, Wd2, Bsde, Cm, Dm, out);
}

// round 16
// speedup vs baseline: 1.1448x; 1.1448x over previous
#include <cuda_runtime.h>
#include <cuda_fp16.h>
#include <cstdint>
#include <math.h>

// ============================================================================
// ConditionedLatentSDETransition — R16: R14 GEMM core + dual-stream overlap
//   main stream: A1 -> bn1 -> A2 -> bn2 -> F -> (join) z_update   [critical path]
//   side stream: Th -> G                                           [fills idle SMs]
//   Cross-stream deps via events recorded during graph capture.
//   MODE 0: zh@W1^T -> A1h + BN stats        grid(8,32)  K=512
//   MODE 5: zh@Wd1^T -> tanh -> Th           grid(4,32)  K=512   [side]
//   MODE 1: bn_relu(A1h)@W2^T -> A2h + stats grid(8,32)  K=1024
//   MODE 2: bn_relu(A2h)@W3^T -> Fh          grid(4,32)  K=1024
//   MODE 4: Th@Wd2^T -> softplus -> Gh       grid(4,32)  K=512   [side]
//   MODE 3: z + dt*(ut@B^T) -> zbuf,out      grid(4,32)  K=64
// ============================================================================

#define BM 128
#define BK 32
#define KS_LD 40
#define NSTG 4
#define SMEM_SZ (2 * NSTG * BM * KS_LD * 2)   // 81920 bytes

#define BATCH 4096
#define DDIM  512
#define HDIM  1024
#define NSTEPS 8

// ---- scratch (device globals; no allocation allowed) ----
__device__ float  g_zbuf[BATCH * DDIM];
__device__ float  g_psum [64 * HDIM];
__device__ float  g_psum2[64 * HDIM];

__device__ __half g_sch[HDIM];
__device__ __half g_shh[HDIM];
__device__ __half g_zh [BATCH * DDIM];
__device__ __half g_A1h[BATCH * HDIM];
__device__ __half g_A2h[BATCH * HDIM];
__device__ __half g_Th [BATCH * DDIM];
__device__ __half g_Fh [BATCH * DDIM];
__device__ __half g_Gh [BATCH * DDIM];
__device__ __half g_W1h [HDIM * DDIM];
__device__ __half g_W2h [HDIM * HDIM];
__device__ __half g_W3h [DDIM * HDIM];
__device__ __half g_Wd1h[DDIM * DDIM];
__device__ __half g_Wd2h[DDIM * DDIM];
__device__ __half g_Bsh [DDIM * 64];
__device__ __half g_uth [BATCH * 64];

__device__ __forceinline__ float softplus_f(float x) {
    return fmaxf(x, 0.f) + log1pf(expf(-fabsf(x)));   // jax.nn.softplus
}
__device__ __forceinline__ void cp16(void* sdst, const void* gsrc) {
    uint32_t sa = (uint32_t)__cvta_generic_to_shared(sdst);
    asm volatile("cp.async.cg.shared.global [%0], [%1], 16;" :: "r"(sa), "l"(gsrc));
}
__device__ __forceinline__ void cp_commit() { asm volatile("cp.async.commit_group;"); }
__device__ __forceinline__ void cp_wait2()  { asm volatile("cp.async.wait_group 2;"); }
__device__ __forceinline__ void ldsm4(uint32_t* r, const void* p) {
    uint32_t a = (uint32_t)__cvta_generic_to_shared(p);
    asm volatile("ldmatrix.sync.aligned.m8n8.x4.shared.b16 {%0,%1,%2,%3}, [%4];"
                 : "=r"(r[0]), "=r"(r[1]), "=r"(r[2]), "=r"(r[3]) : "r"(a));
}
__device__ __forceinline__ void mma_f16(float* c, const uint32_t* a, const uint32_t* b) {
    asm volatile(
        "mma.sync.aligned.m16n8k16.row.col.f32.f16.f16.f32 "
        "{%0,%1,%2,%3}, {%4,%5,%6,%7}, {%8,%9}, {%0,%1,%2,%3};\n"
        : "+f"(c[0]), "+f"(c[1]), "+f"(c[2]), "+f"(c[3])
        : "r"(a[0]), "r"(a[1]), "r"(a[2]), "r"(a[3]), "r"(b[0]), "r"(b[1]));
}

// ---------------------------------------------------------------------------
// One-purpose GEMM kernels (proven R14 mainloop).
// MODE 0: A1 (stats)  1: A2 (BN-staged, stats)  2: F (BN-staged)
// MODE 4: G (softplus) 5: Th (tanh)  3: final z_next
// ---------------------------------------------------------------------------
template<int MODE>
__global__ __launch_bounds__(256, 2)
void gemm16(const float* __restrict__ bias,
            const float* __restrict__ dtp, float* __restrict__ dout)
{
    extern __shared__ __half sh[];
    __half* Asm = sh;
    __half* Bsm = sh + NSTG * BM * KS_LD;

    const int tid = threadIdx.x, lane = tid & 31, wid = tid >> 5;
    const int wm = wid >> 2, wn = wid & 3, grp = lane >> 2, qk = lane & 3;
    const int bx = blockIdx.x, by = blockIdx.y;
    const int bm = by * BM;
    const int row0 = tid >> 2, seg8 = (tid & 3) << 3;

    int K;
    const __half *Aop, *Wslab;
    if (MODE == 0)      { K = 512;  Aop = g_zh;  Wslab = g_W1h  + (size_t)bx * 128 * 512;  }
    else if (MODE == 5) { K = 512;  Aop = g_zh;  Wslab = g_Wd1h + (size_t)bx * 128 * 512;  }
    else if (MODE == 1) { K = 1024; Aop = g_A1h; Wslab = g_W2h  + (size_t)bx * 128 * 1024; }
    else if (MODE == 2) { K = 1024; Aop = g_A2h; Wslab = g_W3h  + (size_t)bx * 128 * 1024; }
    else if (MODE == 4) { K = 512;  Aop = g_Th;  Wslab = g_Wd2h + (size_t)bx * 128 * 512;  }
    else                { K = 64;   Aop = g_uth; Wslab = g_Bsh  + (size_t)bx * 128 * 64;   }
    const bool trA = (MODE == 1) || (MODE == 2);

    const __half* Ap0 = Aop + (size_t)(bm + row0) * K + seg8;
    const __half* Ap1 = Ap0 + (size_t)64 * K;
    const __half* Wp0 = Wslab + (size_t)row0 * K + seg8;
    const __half* Wp1 = Wp0 + (size_t)64 * K;

    float dtv = 0.f;
    if (MODE == 3) dtv = *dtp;

    float c[4][4][4];
#pragma unroll
    for (int mi = 0; mi < 4; mi++)
#pragma unroll
        for (int ni = 0; ni < 4; ni++)
#pragma unroll
            for (int j = 0; j < 4; j++) c[mi][ni][j] = 0.f;

    const int a_r = lane & 15;
    const int a_k = (lane >> 4) << 3;
    const int b_r = (lane & 7) + ((lane >> 4) << 3);
    const int b_k = ((lane >> 3) & 1) << 3;

    uint4 a0r, a1r;

    auto ldgA = [&](int t) {
        const size_t o = (size_t)t * BK;
        a0r = *(const uint4*)(Ap0 + o);
        a1r = *(const uint4*)(Ap1 + o);
    };
    auto cpA = [&](int t, int slot) {
        const size_t o = (size_t)t * BK;
        cp16(Asm + (slot * BM + row0)      * KS_LD + seg8, Ap0 + o);
        cp16(Asm + (slot * BM + row0 + 64) * KS_LD + seg8, Ap1 + o);
    };
    auto cpB = [&](int t, int slot) {
        const size_t o = (size_t)t * BK;
        cp16(Bsm + (slot * BM + row0)      * KS_LD + seg8, Wp0 + o);
        cp16(Bsm + (slot * BM + row0 + 64) * KS_LD + seg8, Wp1 + o);
    };
    auto trsts = [&](int t, int slot) {
        const int kb = t * BK + seg8;
        uint4 sc = *(const uint4*)(g_sch + kb);
        uint4 sf = *(const uint4*)(g_shh + kb);
        __half2* s2 = (__half2*)&sc;
        __half2* f2 = (__half2*)&sf;
        uint4 o0 = a0r, o1 = a1r;
        __half2* h0 = (__half2*)&o0;
        __half2* h1 = (__half2*)&o1;
        const __half2 z2 = __float2half2_rn(0.f);
#pragma unroll
        for (int q = 0; q < 4; q++) {
            h0[q] = __hmax2(__hfma2(h0[q], s2[q], f2[q]), z2);
            h1[q] = __hmax2(__hfma2(h1[q], s2[q], f2[q]), z2);
        }
        *(uint4*)&Asm[(slot * BM + row0)      * KS_LD + seg8] = o0;
        *(uint4*)&Asm[(slot * BM + row0 + 64) * KS_LD + seg8] = o1;
    };

    const int T = K / BK;

#pragma unroll
    for (int p = 0; p < 3; p++) {
        if (p < T) {
            if (trA) ldgA(p); else cpA(p, p);
            cpB(p, p);
            cp_commit();
            if (trA) trsts(p, p);
        } else {
            cp_commit();
        }
    }

    for (int t = 0; t < T; t++) {
        cp_wait2();
        __syncthreads();

        const int tf = t + 3;
        const int slot = tf & 3;
        const bool have = tf < T;
        if (have) {
            if (trA) ldgA(tf); else cpA(tf, slot);
            cpB(tf, slot);
        }
        cp_commit();

        const int sb = t & 3;
#pragma unroll
        for (int ks = 0; ks < 2; ks++) {
            const int kk = ks * 16;
            uint32_t af[4][4], bf[4][2];
#pragma unroll
            for (int mi = 0; mi < 4; mi++)
                ldsm4(af[mi], Asm + (sb * BM + wm * 64 + mi * 16 + a_r) * KS_LD + kk + a_k);
#pragma unroll
            for (int nip = 0; nip < 2; nip++) {
                uint32_t tt[4];
                ldsm4(tt, Bsm + (sb * BM + wn * 32 + nip * 16 + b_r) * KS_LD + kk + b_k);
                bf[2 * nip][0] = tt[0]; bf[2 * nip][1] = tt[1];
                bf[2 * nip + 1][0] = tt[2]; bf[2 * nip + 1][1] = tt[3];
            }
#pragma unroll
            for (int mi = 0; mi < 4; mi++)
#pragma unroll
                for (int ni = 0; ni < 4; ni++)
                    mma_f16(c[mi][ni], af[mi], bf[ni]);
        }

        if (have && trA) trsts(tf, slot);
    }

    // ---- epilogue ----
    float s1x[4], s1y[4], s2x[4], s2y[4];
    const bool do_stats = (MODE == 0) || (MODE == 1);
    if (do_stats) {
#pragma unroll
        for (int ni = 0; ni < 4; ni++) { s1x[ni]=0.f; s1y[ni]=0.f; s2x[ni]=0.f; s2y[ni]=0.f; }
    }

#pragma unroll
    for (int mi = 0; mi < 4; mi++) {
#pragma unroll
        for (int ni = 0; ni < 4; ni++) {
            const int r0 = bm + wm * 64 + mi * 16 + grp;
            const int lc = wn * 32 + ni * 8 + (qk << 1);
            const int cn = bx * 128 + lc;
#pragma unroll
            for (int h = 0; h < 2; h++) {
                const int r = r0 + h * 8;
                const float ax = c[mi][ni][2 * h];
                const float ay = c[mi][ni][2 * h + 1];
                if (MODE == 0 || MODE == 1) {
                    const size_t off = (size_t)r * HDIM + cn;
                    float2 b2 = *(const float2*)(bias + cn);
                    float vx = ax + b2.x, vy = ay + b2.y;
                    __half* dst = (MODE == 0) ? g_A1h : g_A2h;
                    *(__half2*)(dst + off) = __floats2half2_rn(vx, vy);
                    s1x[ni] += vx; s2x[ni] = fmaf(vx, vx, s2x[ni]);
                    s1y[ni] += vy; s2y[ni] = fmaf(vy, vy, s2y[ni]);
                } else if (MODE == 5) {
                    const size_t off = (size_t)r * DDIM + cn;
                    float2 b2 = *(const float2*)(bias + cn);
                    *(__half2*)(g_Th + off) =
                        __floats2half2_rn(tanhf(ax + b2.x), tanhf(ay + b2.y));
                } else if (MODE == 2) {
                    const size_t off = (size_t)r * DDIM + cn;
                    float2 b2 = *(const float2*)(bias + cn);
                    *(__half2*)(g_Fh + off) = __floats2half2_rn(ax + b2.x, ay + b2.y);
                } else if (MODE == 4) {
                    const size_t off = (size_t)r * DDIM + cn;
                    float2 b2 = *(const float2*)(bias + cn);
                    *(__half2*)(g_Gh + off) =
                        __floats2half2_rn(softplus_f(ax + b2.x) + 1e-5f,
                                          softplus_f(ay + b2.y) + 1e-5f);
                } else { // MODE 3
                    const size_t off = (size_t)r * DDIM + cn;
                    float2 zf = *(const float2*)(g_zbuf + off);
                    zf.x = fmaf(dtv, ax, zf.x);
                    zf.y = fmaf(dtv, ay, zf.y);
                    *(float2*)(g_zbuf + off) = zf;
                    *(float2*)(dout + off)   = zf;
                }
            }
        }
    }

    if (do_stats) {
        const int slot = by * 2 + wm;
#pragma unroll
        for (int ni = 0; ni < 4; ni++) {
            float a = s1x[ni], b = s1y[ni], p = s2x[ni], q = s2y[ni];
#pragma unroll
            for (int m = 4; m <= 16; m <<= 1) {
                a += __shfl_xor_sync(0xffffffffu, a, m);
                b += __shfl_xor_sync(0xffffffffu, b, m);
                p += __shfl_xor_sync(0xffffffffu, p, m);
                q += __shfl_xor_sync(0xffffffffu, q, m);
            }
            if (lane < 4) {
                const int cn = bx * 128 + wn * 32 + ni * 8 + (qk << 1);
                *(float2*)&g_psum [slot * HDIM + cn] = make_float2(a, b);
                *(float2*)&g_psum2[slot * HDIM + cn] = make_float2(p, q);
            }
        }
    }
}

// ---------------------------------------------------------------------------
// BN final reduce -> fp16 scale/shift. grid = 16 blocks, 256 threads.
// ---------------------------------------------------------------------------
__global__ void bnstat_final(const float* __restrict__ g, const float* __restrict__ be)
{
    __shared__ float sm1[256], sm2[256];
    const int tid = threadIdx.x;
    const int cl  = tid & 63;
    const int r0  = tid >> 6;
    const int c   = blockIdx.x * 64 + cl;
    float s = 0.f, s2 = 0.f;
#pragma unroll
    for (int r = r0; r < 64; r += 4) {
        s  += g_psum [r * HDIM + c];
        s2 += g_psum2[r * HDIM + c];
    }
    sm1[tid] = s; sm2[tid] = s2;
    __syncthreads();
    if (tid < 64) {
        s  = sm1[tid] + sm1[tid + 64] + sm1[tid + 128] + sm1[tid + 192];
        s2 = sm2[tid] + sm2[tid + 64] + sm2[tid + 128] + sm2[tid + 192];
        const float mu  = s * (1.f / (float)BATCH);
        const float var = fmaf(-mu, mu, s2 * (1.f / (float)BATCH));
        const int cc = blockIdx.x * 64 + tid;
        const float sc = g[cc] / sqrtf(var + 1e-5f);
        g_sch[cc] = __float2half(sc);
        g_shh[cc] = __float2half(fmaf(-mu, sc, be[cc]));
    }
}

// Euler-Maruyama: z = zin + h*F + sqrt_h*G*eps  (F/G fp16)
__global__ void z_update(const float* __restrict__ dtp,
                         const float* __restrict__ eps,
                         const float* __restrict__ zin)
{
    const int i4 = blockIdx.x * blockDim.x + threadIdx.x;
    if (i4 >= BATCH * DDIM / 4) return;
    const float dt = *dtp;
    const float h  = dt * (1.f / (float)NSTEPS);
    const float sq = sqrtf(fabsf(h) + 1e-8f);

    float4 z = ((const float4*)zin)[i4];
    float4 e = ((const float4*)eps)[i4];
    uint2 fu = *(const uint2*)(g_Fh + (size_t)i4 * 4);
    uint2 gu = *(const uint2*)(g_Gh + (size_t)i4 * 4);
    float2 f01 = __half22float2(*(__half2*)&fu.x);
    float2 f23 = __half22float2(*(__half2*)&fu.y);
    float2 g01 = __half22float2(*(__half2*)&gu.x);
    float2 g23 = __half22float2(*(__half2*)&gu.y);
    z.x = z.x + h * f01.x + sq * g01.x * e.x;
    z.y = z.y + h * f01.y + sq * g01.y * e.y;
    z.z = z.z + h * f23.x + sq * g23.x * e.z;
    z.w = z.w + h * f23.y + sq * g23.y * e.w;
    ((float4*)g_zbuf)[i4] = z;
    __half2 h0 = __floats2half2_rn(z.x, z.y);
    __half2 h1 = __floats2half2_rn(z.z, z.w);
    uint2 u; u.x = *(uint32_t*)&h0; u.y = *(uint32_t*)&h1;
    *(uint2*)(g_zh + (size_t)i4 * 4) = u;
}

// one-shot fp32 -> fp16 conversion of all operands; grid (X, 8)
__global__ void cvt_all(const float* s0, const float* s1, const float* s2,
                        const float* s3, const float* s4, const float* s5,
                        const float* s6, const float* s7)
{
    const float* srcs[8] = {s0, s1, s2, s3, s4, s5, s6, s7};
    __half* dsts[8] = {g_W1h, g_W2h, g_W3h, g_Wd1h, g_Wd2h, g_Bsh, g_uth, g_zh};
    const int ns[8] = {HDIM*DDIM, HDIM*HDIM, DDIM*HDIM, DDIM*DDIM,
                       DDIM*DDIM, DDIM*64, BATCH*64, BATCH*DDIM};
    const int seg = blockIdx.y;
    const float* s = srcs[seg];
    __half* d = dsts[seg];
    const int n = ns[seg];
    for (int i = (blockIdx.x * blockDim.x + threadIdx.x) * 8; i < n;
         i += gridDim.x * blockDim.x * 8) {
        float4 v0 = *(const float4*)(s + i);
        float4 v1 = *(const float4*)(s + i + 4);
        __half2 h0 = __floats2half2_rn(v0.x, v0.y);
        __half2 h1 = __floats2half2_rn(v0.z, v0.w);
        __half2 h2 = __floats2half2_rn(v1.x, v1.y);
        __half2 h3 = __floats2half2_rn(v1.z, v1.w);
        uint4 u;
        u.x = *(uint32_t*)&h0; u.y = *(uint32_t*)&h1;
        u.z = *(uint32_t*)&h2; u.w = *(uint32_t*)&h3;
        *(uint4*)(d + i) = u;
    }
}

// yt = z_next @ C^T + (ut*dt) @ D^T  -> out[4096*512 + r*25 + n]  (fp32 exact)
__global__ void yt_k(const float* __restrict__ ut, const float* __restrict__ Cm,
                     const float* __restrict__ Dm, const float* __restrict__ dtp,
                     float* __restrict__ out)
{
    const int i = blockIdx.x * blockDim.x + threadIdx.x;
    if (i >= BATCH * 25) return;
    const int r = i / 25;
    const int n = i - r * 25;

    const float4* zr = (const float4*)(g_zbuf + (size_t)r * DDIM);
    const float4* cr = (const float4*)(Cm + (size_t)n * DDIM);
    float acc = 0.f;
#pragma unroll 8
    for (int k = 0; k < DDIM / 4; k++) {
        float4 a = zr[k], b = cr[k];
        acc += a.x * b.x + a.y * b.y + a.z * b.z + a.w * b.w;
    }
    const float4* ur = (const float4*)(ut + (size_t)r * 64);
    const float4* dr = (const float4*)(Dm + (size_t)n * 64);
    float acc2 = 0.f;
#pragma unroll
    for (int k = 0; k < 16; k++) {
        float4 a = ur[k], b = dr[k];
        acc2 += a.x * b.x + a.y * b.y + a.z * b.z + a.w * b.w;
    }
    out[(size_t)BATCH * DDIM + i] = acc + (*dtp) * acc2;
}

// ===========================================================================
extern "C" void kernel_launch(void* const* d_in, const int* in_sizes, int n_in,
                              void* d_out, int out_size)
{
    (void)in_sizes; (void)n_in; (void)out_size;

    const float* z_dyn = (const float*)d_in[0];
    /* d_in[1] = z_static : unused by reference */
    const float* dtp   = (const float*)d_in[2];
    const float* ut    = (const float*)d_in[3];
    const float* eps   = (const float*)d_in[4];
    const float* W1  = (const float*)d_in[5];
    const float* b1  = (const float*)d_in[6];
    const float* g1  = (const float*)d_in[7];
    const float* be1 = (const float*)d_in[8];
    const float* W2  = (const float*)d_in[9];
    const float* b2  = (const float*)d_in[10];
    const float* g2  = (const float*)d_in[11];
    const float* be2 = (const float*)d_in[12];
    const float* W3  = (const float*)d_in[13];
    const float* b3  = (const float*)d_in[14];
    const float* Wd1 = (const float*)d_in[15];
    const float* bd1 = (const float*)d_in[16];
    const float* Wd2 = (const float*)d_in[17];
    const float* bd2 = (const float*)d_in[18];
    const float* Bsde= (const float*)d_in[19];
    const float* Cm  = (const float*)d_in[20];
    const float* Dm  = (const float*)d_in[21];
    float* out = (float*)d_out;

    float* zbuf;
    cudaGetSymbolAddress((void**)&zbuf, g_zbuf);

    cudaFuncSetAttribute(gemm16<0>, cudaFuncAttributeMaxDynamicSharedMemorySize, SMEM_SZ);
    cudaFuncSetAttribute(gemm16<1>, cudaFuncAttributeMaxDynamicSharedMemorySize, SMEM_SZ);
    cudaFuncSetAttribute(gemm16<2>, cudaFuncAttributeMaxDynamicSharedMemorySize, SMEM_SZ);
    cudaFuncSetAttribute(gemm16<3>, cudaFuncAttributeMaxDynamicSharedMemorySize, SMEM_SZ);
    cudaFuncSetAttribute(gemm16<4>, cudaFuncAttributeMaxDynamicSharedMemorySize, SMEM_SZ);
    cudaFuncSetAttribute(gemm16<5>, cudaFuncAttributeMaxDynamicSharedMemorySize, SMEM_SZ);

    // side stream + fork/join events (host handles; created per call, leaked —
    // a handful of calls total, no device memory involved)
    cudaStream_t s2;
    cudaStreamCreateWithFlags(&s2, cudaStreamNonBlocking);
    cudaEvent_t evCvt, evZ[NSTEPS], evG[NSTEPS];
    cudaEventCreateWithFlags(&evCvt, cudaEventDisableTiming);
    for (int s = 0; s < NSTEPS; s++) {
        cudaEventCreateWithFlags(&evZ[s], cudaEventDisableTiming);
        cudaEventCreateWithFlags(&evG[s], cudaEventDisableTiming);
    }

    const dim3 blk(256);

    // one-shot conversions (weights, ut, z)
    cvt_all<<<dim3(256, 8), 256>>>(W1, W2, W3, Wd1, Wd2, Bsde, ut, z_dyn);
    cudaEventRecord(evCvt, 0);

    for (int s = 0; s < NSTEPS; s++) {
        const float* eps_s = eps + (size_t)s * BATCH * DDIM;
        const float* zsrc  = (s == 0) ? z_dyn : zbuf;

        // ---- side chain: Th -> G (needs zh of this step) ----
        cudaStreamWaitEvent(s2, (s == 0) ? evCvt : evZ[s - 1], 0);
        gemm16<5><<<dim3(4, 32), blk, SMEM_SZ, s2>>>(bd1, dtp, nullptr);
        gemm16<4><<<dim3(4, 32), blk, SMEM_SZ, s2>>>(bd2, dtp, nullptr);
        cudaEventRecord(evG[s], s2);

        // ---- main chain: A1 -> bn1 -> A2 -> bn2 -> F ----
        gemm16<0><<<dim3(8, 32), blk, SMEM_SZ>>>(b1, dtp, nullptr);
        bnstat_final<<<16, 256>>>(g1, be1);
        gemm16<1><<<dim3(8, 32), blk, SMEM_SZ>>>(b2, dtp, nullptr);
        bnstat_final<<<16, 256>>>(g2, be2);
        gemm16<2><<<dim3(4, 32), blk, SMEM_SZ>>>(b3, dtp, nullptr);

        // ---- join + Euler-Maruyama update ----
        cudaStreamWaitEvent(0, evG[s], 0);
        z_update<<<(BATCH * DDIM / 4 + 255) / 256, 256>>>(dtp, eps_s, zsrc);
        cudaEventRecord(evZ[s], 0);
    }

    // z_next = z + dt*(ut @ B_sde^T) -> zbuf and out[0 : 4096*512)
    gemm16<3><<<dim3(4, 32), blk, SMEM_SZ>>>(nullptr, dtp, out);
    // yt -> out[4096*512 : +4096*25)
    yt_k<<<(BATCH * 25 + 255) / 256, 256>>>(ut, Cm, Dm, dtp, out);
}

// round 17
// speedup vs baseline: 1.1701x; 1.0221x over previous
#include <cuda_runtime.h>
#include <cuda_fp16.h>
#include <cstdint>
#include <math.h>

// ============================================================================
// ConditionedLatentSDETransition — R17: R16 + split-K F GEMM
//   main stream: A1 -> bn1 -> A2 -> bn2 -> F(split-K, 256 CTAs) -> z_update
//   side stream: Th -> G
//   MODE 0: zh@W1^T -> A1h + BN stats        grid(8,32)  K=512
//   MODE 5: zh@Wd1^T -> tanh -> Th           grid(4,32)  K=512   [side]
//   MODE 1: bn_relu(A1h)@W2^T -> A2h + stats grid(8,32)  K=1024
//   MODE 2: bn_relu(A2h)@W3^T -> F0/F1 fp32  grid(8,32)  split-K (2 x K=512)
//   MODE 4: Th@Wd2^T -> softplus -> Gh       grid(4,32)  K=512   [side]
//   MODE 3: z + dt*(ut@B^T) -> zbuf,out      grid(4,32)  K=64
// ============================================================================

#define BM 128
#define BK 32
#define KS_LD 40
#define NSTG 4
#define SMEM_SZ (2 * NSTG * BM * KS_LD * 2)   // 81920 bytes

#define BATCH 4096
#define DDIM  512
#define HDIM  1024
#define NSTEPS 8

// ---- scratch (device globals; no allocation allowed) ----
__device__ float  g_zbuf[BATCH * DDIM];
__device__ float  g_psum [64 * HDIM];
__device__ float  g_psum2[64 * HDIM];
__device__ float  g_F0[BATCH * DDIM];
__device__ float  g_F1[BATCH * DDIM];

__device__ __half g_sch[HDIM];
__device__ __half g_shh[HDIM];
__device__ __half g_zh [BATCH * DDIM];
__device__ __half g_A1h[BATCH * HDIM];
__device__ __half g_A2h[BATCH * HDIM];
__device__ __half g_Th [BATCH * DDIM];
__device__ __half g_Gh [BATCH * DDIM];
__device__ __half g_W1h [HDIM * DDIM];
__device__ __half g_W2h [HDIM * HDIM];
__device__ __half g_W3h [DDIM * HDIM];
__device__ __half g_Wd1h[DDIM * DDIM];
__device__ __half g_Wd2h[DDIM * DDIM];
__device__ __half g_Bsh [DDIM * 64];
__device__ __half g_uth [BATCH * 64];

__device__ __forceinline__ float softplus_f(float x) {
    return fmaxf(x, 0.f) + log1pf(expf(-fabsf(x)));   // jax.nn.softplus
}
__device__ __forceinline__ void cp16(void* sdst, const void* gsrc) {
    uint32_t sa = (uint32_t)__cvta_generic_to_shared(sdst);
    asm volatile("cp.async.cg.shared.global [%0], [%1], 16;" :: "r"(sa), "l"(gsrc));
}
__device__ __forceinline__ void cp_commit() { asm volatile("cp.async.commit_group;"); }
__device__ __forceinline__ void cp_wait2()  { asm volatile("cp.async.wait_group 2;"); }
__device__ __forceinline__ void ldsm4(uint32_t* r, const void* p) {
    uint32_t a = (uint32_t)__cvta_generic_to_shared(p);
    asm volatile("ldmatrix.sync.aligned.m8n8.x4.shared.b16 {%0,%1,%2,%3}, [%4];"
                 : "=r"(r[0]), "=r"(r[1]), "=r"(r[2]), "=r"(r[3]) : "r"(a));
}
__device__ __forceinline__ void mma_f16(float* c, const uint32_t* a, const uint32_t* b) {
    asm volatile(
        "mma.sync.aligned.m16n8k16.row.col.f32.f16.f16.f32 "
        "{%0,%1,%2,%3}, {%4,%5,%6,%7}, {%8,%9}, {%0,%1,%2,%3};\n"
        : "+f"(c[0]), "+f"(c[1]), "+f"(c[2]), "+f"(c[3])
        : "r"(a[0]), "r"(a[1]), "r"(a[2]), "r"(a[3]), "r"(b[0]), "r"(b[1]));
}

// ---------------------------------------------------------------------------
// MODE 0: A1 (stats)  1: A2 (BN-staged, stats)  2: F split-K fp32 partials
// MODE 4: G (softplus) 5: Th (tanh)  3: final z_next
// ---------------------------------------------------------------------------
template<int MODE>
__global__ __launch_bounds__(256, 2)
void gemm16(const float* __restrict__ bias,
            const float* __restrict__ dtp, float* __restrict__ dout)
{
    extern __shared__ __half sh[];
    __half* Asm = sh;
    __half* Bsm = sh + NSTG * BM * KS_LD;

    const int tid = threadIdx.x, lane = tid & 31, wid = tid >> 5;
    const int wm = wid >> 2, wn = wid & 3, grp = lane >> 2, qk = lane & 3;
    const int bx = blockIdx.x, by = blockIdx.y;
    const int bm = by * BM;
    const int row0 = tid >> 2, seg8 = (tid & 3) << 3;

    int Kloop, Kld, koff = 0, bxx = bx, khalf = 0;
    const __half *Aop, *Wslab;
    if (MODE == 0)      { Kloop = 512;  Kld = 512;  Aop = g_zh;  Wslab = g_W1h  + (size_t)bx * 128 * 512;  }
    else if (MODE == 5) { Kloop = 512;  Kld = 512;  Aop = g_zh;  Wslab = g_Wd1h + (size_t)bx * 128 * 512;  }
    else if (MODE == 1) { Kloop = 1024; Kld = 1024; Aop = g_A1h; Wslab = g_W2h  + (size_t)bx * 128 * 1024; }
    else if (MODE == 2) {
        khalf = bx >> 2; bxx = bx & 3;
        Kloop = 512; Kld = 1024; koff = khalf * 512;
        Aop = g_A2h; Wslab = g_W3h + (size_t)bxx * 128 * 1024;
    }
    else if (MODE == 4) { Kloop = 512;  Kld = 512;  Aop = g_Th;  Wslab = g_Wd2h + (size_t)bx * 128 * 512;  }
    else                { Kloop = 64;   Kld = 64;   Aop = g_uth; Wslab = g_Bsh  + (size_t)bx * 128 * 64;   }
    const bool trA = (MODE == 1) || (MODE == 2);

    const __half* Ap0 = Aop + (size_t)(bm + row0) * Kld + koff + seg8;
    const __half* Ap1 = Ap0 + (size_t)64 * Kld;
    const __half* Wp0 = Wslab + (size_t)row0 * Kld + koff + seg8;
    const __half* Wp1 = Wp0 + (size_t)64 * Kld;

    float dtv = 0.f;
    if (MODE == 3) dtv = *dtp;

    float c[4][4][4];
#pragma unroll
    for (int mi = 0; mi < 4; mi++)
#pragma unroll
        for (int ni = 0; ni < 4; ni++)
#pragma unroll
            for (int j = 0; j < 4; j++) c[mi][ni][j] = 0.f;

    const int a_r = lane & 15;
    const int a_k = (lane >> 4) << 3;
    const int b_r = (lane & 7) + ((lane >> 4) << 3);
    const int b_k = ((lane >> 3) & 1) << 3;

    uint4 a0r, a1r;

    auto ldgA = [&](int t) {
        const size_t o = (size_t)t * BK;
        a0r = *(const uint4*)(Ap0 + o);
        a1r = *(const uint4*)(Ap1 + o);
    };
    auto cpA = [&](int t, int slot) {
        const size_t o = (size_t)t * BK;
        cp16(Asm + (slot * BM + row0)      * KS_LD + seg8, Ap0 + o);
        cp16(Asm + (slot * BM + row0 + 64) * KS_LD + seg8, Ap1 + o);
    };
    auto cpB = [&](int t, int slot) {
        const size_t o = (size_t)t * BK;
        cp16(Bsm + (slot * BM + row0)      * KS_LD + seg8, Wp0 + o);
        cp16(Bsm + (slot * BM + row0 + 64) * KS_LD + seg8, Wp1 + o);
    };
    auto trsts = [&](int t, int slot) {
        const int kb = koff + t * BK + seg8;       // absolute k for scale/shift
        uint4 sc = *(const uint4*)(g_sch + kb);
        uint4 sf = *(const uint4*)(g_shh + kb);
        __half2* s2 = (__half2*)&sc;
        __half2* f2 = (__half2*)&sf;
        uint4 o0 = a0r, o1 = a1r;
        __half2* h0 = (__half2*)&o0;
        __half2* h1 = (__half2*)&o1;
        const __half2 z2 = __float2half2_rn(0.f);
#pragma unroll
        for (int q = 0; q < 4; q++) {
            h0[q] = __hmax2(__hfma2(h0[q], s2[q], f2[q]), z2);
            h1[q] = __hmax2(__hfma2(h1[q], s2[q], f2[q]), z2);
        }
        *(uint4*)&Asm[(slot * BM + row0)      * KS_LD + seg8] = o0;
        *(uint4*)&Asm[(slot * BM + row0 + 64) * KS_LD + seg8] = o1;
    };

    const int T = Kloop / BK;

#pragma unroll
    for (int p = 0; p < 3; p++) {
        if (p < T) {
            if (trA) ldgA(p); else cpA(p, p);
            cpB(p, p);
            cp_commit();
            if (trA) trsts(p, p);
        } else {
            cp_commit();
        }
    }

    for (int t = 0; t < T; t++) {
        cp_wait2();
        __syncthreads();

        const int tf = t + 3;
        const int slot = tf & 3;
        const bool have = tf < T;
        if (have) {
            if (trA) ldgA(tf); else cpA(tf, slot);
            cpB(tf, slot);
        }
        cp_commit();

        const int sb = t & 3;
#pragma unroll
        for (int ks = 0; ks < 2; ks++) {
            const int kk = ks * 16;
            uint32_t af[4][4], bf[4][2];
#pragma unroll
            for (int mi = 0; mi < 4; mi++)
                ldsm4(af[mi], Asm + (sb * BM + wm * 64 + mi * 16 + a_r) * KS_LD + kk + a_k);
#pragma unroll
            for (int nip = 0; nip < 2; nip++) {
                uint32_t tt[4];
                ldsm4(tt, Bsm + (sb * BM + wn * 32 + nip * 16 + b_r) * KS_LD + kk + b_k);
                bf[2 * nip][0] = tt[0]; bf[2 * nip][1] = tt[1];
                bf[2 * nip + 1][0] = tt[2]; bf[2 * nip + 1][1] = tt[3];
            }
#pragma unroll
            for (int mi = 0; mi < 4; mi++)
#pragma unroll
                for (int ni = 0; ni < 4; ni++)
                    mma_f16(c[mi][ni], af[mi], bf[ni]);
        }

        if (have && trA) trsts(tf, slot);
    }

    // ---- epilogue ----
    float s1x[4], s1y[4], s2x[4], s2y[4];
    const bool do_stats = (MODE == 0) || (MODE == 1);
    if (do_stats) {
#pragma unroll
        for (int ni = 0; ni < 4; ni++) { s1x[ni]=0.f; s1y[ni]=0.f; s2x[ni]=0.f; s2y[ni]=0.f; }
    }

#pragma unroll
    for (int mi = 0; mi < 4; mi++) {
#pragma unroll
        for (int ni = 0; ni < 4; ni++) {
            const int r0 = bm + wm * 64 + mi * 16 + grp;
            const int lc = wn * 32 + ni * 8 + (qk << 1);
            const int cn = bxx * 128 + lc;
#pragma unroll
            for (int h = 0; h < 2; h++) {
                const int r = r0 + h * 8;
                const float ax = c[mi][ni][2 * h];
                const float ay = c[mi][ni][2 * h + 1];
                if (MODE == 0 || MODE == 1) {
                    const size_t off = (size_t)r * HDIM + cn;
                    float2 b2 = *(const float2*)(bias + cn);
                    float vx = ax + b2.x, vy = ay + b2.y;
                    __half* dst = (MODE == 0) ? g_A1h : g_A2h;
                    *(__half2*)(dst + off) = __floats2half2_rn(vx, vy);
                    s1x[ni] += vx; s2x[ni] = fmaf(vx, vx, s2x[ni]);
                    s1y[ni] += vy; s2y[ni] = fmaf(vy, vy, s2y[ni]);
                } else if (MODE == 5) {
                    const size_t off = (size_t)r * DDIM + cn;
                    float2 b2 = *(const float2*)(bias + cn);
                    *(__half2*)(g_Th + off) =
                        __floats2half2_rn(tanhf(ax + b2.x), tanhf(ay + b2.y));
                } else if (MODE == 2) {
                    const size_t off = (size_t)r * DDIM + cn;
                    float* dst = khalf ? g_F1 : g_F0;
                    float vx = ax, vy = ay;
                    if (!khalf) {   // bias folded into half 0 only
                        float2 b2 = *(const float2*)(bias + cn);
                        vx += b2.x; vy += b2.y;
                    }
                    *(float2*)(dst + off) = make_float2(vx, vy);
                } else if (MODE == 4) {
                    const size_t off = (size_t)r * DDIM + cn;
                    float2 b2 = *(const float2*)(bias + cn);
                    *(__half2*)(g_Gh + off) =
                        __floats2half2_rn(softplus_f(ax + b2.x) + 1e-5f,
                                          softplus_f(ay + b2.y) + 1e-5f);
                } else { // MODE 3
                    const size_t off = (size_t)r * DDIM + cn;
                    float2 zf = *(const float2*)(g_zbuf + off);
                    zf.x = fmaf(dtv, ax, zf.x);
                    zf.y = fmaf(dtv, ay, zf.y);
                    *(float2*)(g_zbuf + off) = zf;
                    *(float2*)(dout + off)   = zf;
                }
            }
        }
    }

    if (do_stats) {
        const int slot = by * 2 + wm;
#pragma unroll
        for (int ni = 0; ni < 4; ni++) {
            float a = s1x[ni], b = s1y[ni], p = s2x[ni], q = s2y[ni];
#pragma unroll
            for (int m = 4; m <= 16; m <<= 1) {
                a += __shfl_xor_sync(0xffffffffu, a, m);
                b += __shfl_xor_sync(0xffffffffu, b, m);
                p += __shfl_xor_sync(0xffffffffu, p, m);
                q += __shfl_xor_sync(0xffffffffu, q, m);
            }
            if (lane < 4) {
                const int cn2 = bx * 128 + wn * 32 + ni * 8 + (qk << 1);
                *(float2*)&g_psum [slot * HDIM + cn2] = make_float2(a, b);
                *(float2*)&g_psum2[slot * HDIM + cn2] = make_float2(p, q);
            }
        }
    }
}

// ---------------------------------------------------------------------------
// BN final reduce -> fp16 scale/shift. grid = 16 blocks, 256 threads.
// ---------------------------------------------------------------------------
__global__ void bnstat_final(const float* __restrict__ g, const float* __restrict__ be)
{
    __shared__ float sm1[256], sm2[256];
    const int tid = threadIdx.x;
    const int cl  = tid & 63;
    const int r0  = tid >> 6;
    const int c   = blockIdx.x * 64 + cl;
    float s = 0.f, s2 = 0.f;
#pragma unroll
    for (int r = r0; r < 64; r += 4) {
        s  += g_psum [r * HDIM + c];
        s2 += g_psum2[r * HDIM + c];
    }
    sm1[tid] = s; sm2[tid] = s2;
    __syncthreads();
    if (tid < 64) {
        s  = sm1[tid] + sm1[tid + 64] + sm1[tid + 128] + sm1[tid + 192];
        s2 = sm2[tid] + sm2[tid + 64] + sm2[tid + 128] + sm2[tid + 192];
        const float mu  = s * (1.f / (float)BATCH);
        const float var = fmaf(-mu, mu, s2 * (1.f / (float)BATCH));
        const int cc = blockIdx.x * 64 + tid;
        const float sc = g[cc] / sqrtf(var + 1e-5f);
        g_sch[cc] = __float2half(sc);
        g_shh[cc] = __float2half(fmaf(-mu, sc, be[cc]));
    }
}

// Euler-Maruyama: z = zin + h*(F0+F1) + sqrt_h*G*eps   (F fp32 partials, G fp16)
__global__ void z_update(const float* __restrict__ dtp,
                         const float* __restrict__ eps,
                         const float* __restrict__ zin)
{
    const int i4 = blockIdx.x * blockDim.x + threadIdx.x;
    if (i4 >= BATCH * DDIM / 4) return;
    const float dt = *dtp;
    const float h  = dt * (1.f / (float)NSTEPS);
    const float sq = sqrtf(fabsf(h) + 1e-8f);

    float4 z  = ((const float4*)zin)[i4];
    float4 e  = ((const float4*)eps)[i4];
    float4 f0 = ((const float4*)g_F0)[i4];
    float4 f1 = ((const float4*)g_F1)[i4];
    uint2 gu = *(const uint2*)(g_Gh + (size_t)i4 * 4);
    float2 g01 = __half22float2(*(__half2*)&gu.x);
    float2 g23 = __half22float2(*(__half2*)&gu.y);
    z.x = z.x + h * (f0.x + f1.x) + sq * g01.x * e.x;
    z.y = z.y + h * (f0.y + f1.y) + sq * g01.y * e.y;
    z.z = z.z + h * (f0.z + f1.z) + sq * g23.x * e.z;
    z.w = z.w + h * (f0.w + f1.w) + sq * g23.y * e.w;
    ((float4*)g_zbuf)[i4] = z;
    __half2 h0 = __floats2half2_rn(z.x, z.y);
    __half2 h1 = __floats2half2_rn(z.z, z.w);
    uint2 u; u.x = *(uint32_t*)&h0; u.y = *(uint32_t*)&h1;
    *(uint2*)(g_zh + (size_t)i4 * 4) = u;
}

// one-shot fp32 -> fp16 conversion of all operands; grid (X, 8)
__global__ void cvt_all(const float* s0, const float* s1, const float* s2,
                        const float* s3, const float* s4, const float* s5,
                        const float* s6, const float* s7)
{
    const float* srcs[8] = {s0, s1, s2, s3, s4, s5, s6, s7};
    __half* dsts[8] = {g_W1h, g_W2h, g_W3h, g_Wd1h, g_Wd2h, g_Bsh, g_uth, g_zh};
    const int ns[8] = {HDIM*DDIM, HDIM*HDIM, DDIM*HDIM, DDIM*DDIM,
                       DDIM*DDIM, DDIM*64, BATCH*64, BATCH*DDIM};
    const int seg = blockIdx.y;
    const float* s = srcs[seg];
    __half* d = dsts[seg];
    const int n = ns[seg];
    for (int i = (blockIdx.x * blockDim.x + threadIdx.x) * 8; i < n;
         i += gridDim.x * blockDim.x * 8) {
        float4 v0 = *(const float4*)(s + i);
        float4 v1 = *(const float4*)(s + i + 4);
        __half2 h0 = __floats2half2_rn(v0.x, v0.y);
        __half2 h1 = __floats2half2_rn(v0.z, v0.w);
        __half2 h2 = __floats2half2_rn(v1.x, v1.y);
        __half2 h3 = __floats2half2_rn(v1.z, v1.w);
        uint4 u;
        u.x = *(uint32_t*)&h0; u.y = *(uint32_t*)&h1;
        u.z = *(uint32_t*)&h2; u.w = *(uint32_t*)&h3;
        *(uint4*)(d + i) = u;
    }
}

// yt = z_next @ C^T + (ut*dt) @ D^T  -> out[4096*512 + r*25 + n]  (fp32 exact)
__global__ void yt_k(const float* __restrict__ ut, const float* __restrict__ Cm,
                     const float* __restrict__ Dm, const float* __restrict__ dtp,
                     float* __restrict__ out)
{
    const int i = blockIdx.x * blockDim.x + threadIdx.x;
    if (i >= BATCH * 25) return;
    const int r = i / 25;
    const int n = i - r * 25;

    const float4* zr = (const float4*)(g_zbuf + (size_t)r * DDIM);
    const float4* cr = (const float4*)(Cm + (size_t)n * DDIM);
    float acc = 0.f;
#pragma unroll 8
    for (int k = 0; k < DDIM / 4; k++) {
        float4 a = zr[k], b = cr[k];
        acc += a.x * b.x + a.y * b.y + a.z * b.z + a.w * b.w;
    }
    const float4* ur = (const float4*)(ut + (size_t)r * 64);
    const float4* dr = (const float4*)(Dm + (size_t)n * 64);
    float acc2 = 0.f;
#pragma unroll
    for (int k = 0; k < 16; k++) {
        float4 a = ur[k], b = dr[k];
        acc2 += a.x * b.x + a.y * b.y + a.z * b.z + a.w * b.w;
    }
    out[(size_t)BATCH * DDIM + i] = acc + (*dtp) * acc2;
}

// ===========================================================================
extern "C" void kernel_launch(void* const* d_in, const int* in_sizes, int n_in,
                              void* d_out, int out_size)
{
    (void)in_sizes; (void)n_in; (void)out_size;

    const float* z_dyn = (const float*)d_in[0];
    /* d_in[1] = z_static : unused by reference */
    const float* dtp   = (const float*)d_in[2];
    const float* ut    = (const float*)d_in[3];
    const float* eps   = (const float*)d_in[4];
    const float* W1  = (const float*)d_in[5];
    const float* b1  = (const float*)d_in[6];
    const float* g1  = (const float*)d_in[7];
    const float* be1 = (const float*)d_in[8];
    const float* W2  = (const float*)d_in[9];
    const float* b2  = (const float*)d_in[10];
    const float* g2  = (const float*)d_in[11];
    const float* be2 = (const float*)d_in[12];
    const float* W3  = (const float*)d_in[13];
    const float* b3  = (const float*)d_in[14];
    const float* Wd1 = (const float*)d_in[15];
    const float* bd1 = (const float*)d_in[16];
    const float* Wd2 = (const float*)d_in[17];
    const float* bd2 = (const float*)d_in[18];
    const float* Bsde= (const float*)d_in[19];
    const float* Cm  = (const float*)d_in[20];
    const float* Dm  = (const float*)d_in[21];
    float* out = (float*)d_out;

    float* zbuf;
    cudaGetSymbolAddress((void**)&zbuf, g_zbuf);

    cudaFuncSetAttribute(gemm16<0>, cudaFuncAttributeMaxDynamicSharedMemorySize, SMEM_SZ);
    cudaFuncSetAttribute(gemm16<1>, cudaFuncAttributeMaxDynamicSharedMemorySize, SMEM_SZ);
    cudaFuncSetAttribute(gemm16<2>, cudaFuncAttributeMaxDynamicSharedMemorySize, SMEM_SZ);
    cudaFuncSetAttribute(gemm16<3>, cudaFuncAttributeMaxDynamicSharedMemorySize, SMEM_SZ);
    cudaFuncSetAttribute(gemm16<4>, cudaFuncAttributeMaxDynamicSharedMemorySize, SMEM_SZ);
    cudaFuncSetAttribute(gemm16<5>, cudaFuncAttributeMaxDynamicSharedMemorySize, SMEM_SZ);

    // side stream + fork/join events (host handles; leaked, few calls total)
    cudaStream_t s2;
    cudaStreamCreateWithFlags(&s2, cudaStreamNonBlocking);
    cudaEvent_t evCvt, evZ[NSTEPS], evG[NSTEPS];
    cudaEventCreateWithFlags(&evCvt, cudaEventDisableTiming);
    for (int s = 0; s < NSTEPS; s++) {
        cudaEventCreateWithFlags(&evZ[s], cudaEventDisableTiming);
        cudaEventCreateWithFlags(&evG[s], cudaEventDisableTiming);
    }

    const dim3 blk(256);

    // one-shot conversions (weights, ut, z)
    cvt_all<<<dim3(256, 8), 256>>>(W1, W2, W3, Wd1, Wd2, Bsde, ut, z_dyn);
    cudaEventRecord(evCvt, 0);

    for (int s = 0; s < NSTEPS; s++) {
        const float* eps_s = eps + (size_t)s * BATCH * DDIM;
        const float* zsrc  = (s == 0) ? z_dyn : zbuf;

        // ---- side chain: Th -> G (needs zh of this step) ----
        cudaStreamWaitEvent(s2, (s == 0) ? evCvt : evZ[s - 1], 0);
        gemm16<5><<<dim3(4, 32), blk, SMEM_SZ, s2>>>(bd1, dtp, nullptr);
        gemm16<4><<<dim3(4, 32), blk, SMEM_SZ, s2>>>(bd2, dtp, nullptr);
        cudaEventRecord(evG[s], s2);

        // ---- main chain: A1 -> bn1 -> A2 -> bn2 -> F(split-K) ----
        gemm16<0><<<dim3(8, 32), blk, SMEM_SZ>>>(b1, dtp, nullptr);
        bnstat_final<<<16, 256>>>(g1, be1);
        gemm16<1><<<dim3(8, 32), blk, SMEM_SZ>>>(b2, dtp, nullptr);
        bnstat_final<<<16, 256>>>(g2, be2);
        gemm16<2><<<dim3(8, 32), blk, SMEM_SZ>>>(b3, dtp, nullptr);

        // ---- join + Euler-Maruyama update ----
        cudaStreamWaitEvent(0, evG[s], 0);
        z_update<<<(BATCH * DDIM / 4 + 255) / 256, 256>>>(dtp, eps_s, zsrc);
        cudaEventRecord(evZ[s], 0);
    }

    // z_next = z + dt*(ut @ B_sde^T) -> zbuf and out[0 : 4096*512)
    gemm16<3><<<dim3(4, 32), blk, SMEM_SZ>>>(nullptr, dtp, out);
    // yt -> out[4096*512 : +4096*25)
    yt_k<<<(BATCH * 25 + 255) / 256, 256>>>(ut, Cm, Dm, dtp, out);
}